// round 8
// baseline (speedup 1.0000x reference)
#include <cuda_runtime.h>
#include <cuda_fp16.h>
#include <cstdint>

typedef uint32_t u32;

#define NPOS    (4096*128)
#define TILE    256
#define NTILES  (NPOS/TILE)    // 2048
#define THREADS 256
#define NBLOCKS 304

#define RSTRIDE 72             // halves per row for weight tiles (ldmatrix conflict-free)

// ---- dynamic SMEM layout (bytes) ----
#define SM_W1F  0              // 64 x float4   (1024)
#define SM_C2   1024           // 64 f          (256)
#define SM_C3   1280           // 128 f         (512)
#define SM_W2   1792           // 64  x 72 h    (9216)
#define SM_W3   11008          // 128 x 72 h    (18432)
#define SMEM_TOTAL 29440

static __device__ __forceinline__ u32 sptr(const void* p) {
    u32 a;
    asm("{ .reg .u64 t; cvta.to.shared.u64 t, %1; cvt.u32.u64 %0, t; }" : "=r"(a) : "l"(p));
    return a;
}
static __device__ __forceinline__ void ldm4(u32& r0, u32& r1, u32& r2, u32& r3, u32 addr) {
    asm volatile("ldmatrix.sync.aligned.m8n8.x4.shared.b16 {%0,%1,%2,%3}, [%4];"
                 : "=r"(r0), "=r"(r1), "=r"(r2), "=r"(r3) : "r"(addr));
}
static __device__ __forceinline__ void mma16816(float c[4], const u32 a[4], u32 b0, u32 b1) {
    asm volatile("mma.sync.aligned.m16n8k16.row.col.f32.f16.f16.f32 "
                 "{%0,%1,%2,%3}, {%4,%5,%6,%7}, {%8,%9}, {%0,%1,%2,%3};"
                 : "+f"(c[0]), "+f"(c[1]), "+f"(c[2]), "+f"(c[3])
                 : "r"(a[0]), "r"(a[1]), "r"(a[2]), "r"(a[3]), "r"(b0), "r"(b1));
}
static __device__ __forceinline__ u32 pack2(float a, float b) {
    __half2 h = __floats2half2_rn(a, b);
    return *reinterpret_cast<u32*>(&h);
}

extern "C" __global__ void __launch_bounds__(THREADS, 2)
pn_mma_kernel(const float* __restrict__ pc,  const float* __restrict__ valid,
              const float* __restrict__ W1,  const float* __restrict__ b1,
              const float* __restrict__ g1,  const float* __restrict__ be1,
              const float* __restrict__ m1,  const float* __restrict__ v1,
              const float* __restrict__ W2,  const float* __restrict__ b2,
              const float* __restrict__ g2,  const float* __restrict__ be2,
              const float* __restrict__ m2,  const float* __restrict__ v2,
              const float* __restrict__ W3,  const float* __restrict__ b3,
              const float* __restrict__ g3,  const float* __restrict__ be3,
              const float* __restrict__ m3,  const float* __restrict__ v3,
              float* __restrict__ out)
{
    extern __shared__ char smem[];
    const u32 sb = sptr(smem);
    const int t    = threadIdx.x;
    const int lane = t & 31;
    const int w    = t >> 5;

    float4* s_w1f = reinterpret_cast<float4*>(smem + SM_W1F);
    float*  s_c2  = reinterpret_cast<float*>(smem + SM_C2);
    float*  s_c3  = reinterpret_cast<float*>(smem + SM_C3);
    __half* s_w2  = reinterpret_cast<__half*>(smem + SM_W2);
    __half* s_w3  = reinterpret_cast<__half*>(smem + SM_W3);

    // ---- one-time prep: fold BN, convert weights to fp16 ----
    if (t < 64) {
        float inv1 = g1[t] * rsqrtf(v1[t] + 1e-5f);
        s_w1f[t] = make_float4(W1[3*t+0]*inv1, W1[3*t+1]*inv1, W1[3*t+2]*inv1,
                               be1[t] + (b1[t] - m1[t]) * inv1);
        float inv2 = g2[t] * rsqrtf(v2[t] + 1e-5f);
        s_c2[t] = be2[t] + (b2[t] - m2[t]) * inv2;
    }
    if (t < 128) {
        float inv3 = g3[t] * rsqrtf(v3[t] + 1e-5f);
        s_c3[t] = be3[t] + (b3[t] - m3[t]) * inv3;
    }
    for (int i = t; i < 64*64; i += THREADS) {
        int n = i >> 6, k = i & 63;
        float inv2 = g2[n] * rsqrtf(v2[n] + 1e-5f);
        s_w2[n*RSTRIDE + k] = __float2half_rn(W2[i] * inv2);
    }
    for (int i = t; i < 128*64; i += THREADS) {
        int n = i >> 6, k = i & 63;
        float inv3 = g3[n] * rsqrtf(v3[n] + 1e-5f);
        s_w3[n*RSTRIDE + k] = __float2half_rn(W3[i] * inv3);
    }
    __syncthreads();   // weights ready; no further block syncs

    // ---- per-thread fragment geometry ----
    const int qr  = lane >> 2;                            // fragment row r
    const int qc  = (lane & 3) * 2;                       // fragment col pair base
    const int lr8 = (lane & 7) + ((lane >> 3) & 1) * 8;
    const int lc8 = (lane >> 4) * 8;

    const u32 w2base = sb + SM_W2 + (u32)(((lane & 15)*RSTRIDE + lc8)*2);
    const u32 w3base = sb + SM_W3 + (u32)((lr8*RSTRIDE + lc8)*2);

    // ---- prefetch first tile (lane holds pos w*32+lane) ----
    int tile = blockIdx.x;
    float x0 = 0.f, x1 = 0.f, x2 = 0.f, vld = 0.f;
    if (tile < NTILES) {
        int px = tile*TILE + w*32 + lane;
        x0 = pc[px]; x1 = pc[NPOS + px]; x2 = pc[2*NPOS + px];
        vld = valid[px];
    }

    for (; tile < NTILES; tile += gridDim.x) {
        const int p0 = tile * TILE;

        // ---- distribute x to fragment rows via shuffle ----
        // thread needs pos rows j=0..3 -> w*32 + {r, r+8, r+16, r+24}
        float xr0[4], xr1[4], xr2[4];
        #pragma unroll
        for (int j = 0; j < 4; ++j) {
            int src = qr + 8*j;
            xr0[j] = __shfl_sync(0xffffffffu, x0, src);
            xr1[j] = __shfl_sync(0xffffffffu, x1, src);
            xr2[j] = __shfl_sync(0xffffffffu, x2, src);
        }
        // valid for epilogue columns
        float2 vv[2][2];
        #pragma unroll
        for (int pb = 0; pb < 2; ++pb)
            #pragma unroll
            for (int h = 0; h < 2; ++h) {
                int src = pb*16 + h*8 + qc;
                vv[pb][h].x = __shfl_sync(0xffffffffu, vld, src);
                vv[pb][h].y = __shfl_sync(0xffffffffu, vld, src + 1);
            }

        // ---- prefetch next tile (LDG latency hidden under MMAs) ----
        {
            int ntile = tile + gridDim.x;
            x0 = x1 = x2 = vld = 0.f;
            if (ntile < NTILES) {
                int px = ntile*TILE + w*32 + lane;
                x0 = pc[px]; x1 = pc[NPOS + px]; x2 = pc[2*NPOS + px];
                vld = valid[px];
            }
        }

        // ---- layer 2 with on-the-fly layer-1 A fragments ----
        float acc2[2][8][4];
        #pragma unroll
        for (int nt = 0; nt < 8; ++nt) {
            float2 bb = *reinterpret_cast<const float2*>(&s_c2[nt*8 + qc]);
            #pragma unroll
            for (int pb = 0; pb < 2; ++pb) {
                acc2[pb][nt][0] = bb.x; acc2[pb][nt][1] = bb.y;
                acc2[pb][nt][2] = bb.x; acc2[pb][nt][3] = bb.y;
            }
        }
        #pragma unroll
        for (int kt = 0; kt < 4; ++kt) {
            // channels this lane contributes at this k-step
            const int k0 = 16*kt + qc;
            float4 wk0 = s_w1f[k0], wk1 = s_w1f[k0+1], wk2 = s_w1f[k0+8], wk3 = s_w1f[k0+9];
            u32 aA[4], aB[4];
            #pragma unroll
            for (int pb = 0; pb < 2; ++pb) {
                u32* a = pb ? aB : aA;
                #pragma unroll
                for (int rr = 0; rr < 2; ++rr) {
                    int j = pb*2 + rr;
                    float y0 = fmaf(wk0.x, xr0[j], fmaf(wk0.y, xr1[j], fmaf(wk0.z, xr2[j], wk0.w)));
                    float y1 = fmaf(wk1.x, xr0[j], fmaf(wk1.y, xr1[j], fmaf(wk1.z, xr2[j], wk1.w)));
                    float y2 = fmaf(wk2.x, xr0[j], fmaf(wk2.y, xr1[j], fmaf(wk2.z, xr2[j], wk2.w)));
                    float y3 = fmaf(wk3.x, xr0[j], fmaf(wk3.y, xr1[j], fmaf(wk3.z, xr2[j], wk3.w)));
                    a[rr]     = pack2(fmaxf(y0, 0.f), fmaxf(y1, 0.f));
                    a[2 + rr] = pack2(fmaxf(y2, 0.f), fmaxf(y3, 0.f));
                }
            }
            #pragma unroll
            for (int np = 0; np < 4; ++np) {
                u32 b[4];
                ldm4(b[0], b[1], b[2], b[3], w2base + np*(16*RSTRIDE*2) + kt*32);
                // x4 fill: b0=(n0-7,klo) b1=(n8-15,klo) b2=(n0-7,khi) b3=(n8-15,khi)
                mma16816(acc2[0][2*np],   aA, b[0], b[2]);
                mma16816(acc2[0][2*np+1], aA, b[1], b[3]);
                mma16816(acc2[1][2*np],   aB, b[0], b[2]);
                mma16816(acc2[1][2*np+1], aB, b[1], b[3]);
            }
        }

        // ---- relu+pack acc2 -> layer3 B fragments (registers) ----
        u32 y2b[2][4][2][2];
        #pragma unroll
        for (int pb = 0; pb < 2; ++pb)
            #pragma unroll
            for (int kt = 0; kt < 4; ++kt) {
                y2b[pb][kt][0][0] = pack2(fmaxf(acc2[pb][2*kt][0],   0.f), fmaxf(acc2[pb][2*kt][1],   0.f));
                y2b[pb][kt][0][1] = pack2(fmaxf(acc2[pb][2*kt+1][0], 0.f), fmaxf(acc2[pb][2*kt+1][1], 0.f));
                y2b[pb][kt][1][0] = pack2(fmaxf(acc2[pb][2*kt][2],   0.f), fmaxf(acc2[pb][2*kt][3],   0.f));
                y2b[pb][kt][1][1] = pack2(fmaxf(acc2[pb][2*kt+1][2], 0.f), fmaxf(acc2[pb][2*kt+1][3], 0.f));
            }

        // ---- layer 3: [out3 128][pos 32] per warp ----
        {
            float* outb = out + (size_t)p0 + w*32;
            #pragma unroll
            for (int ob = 0; ob < 8; ++ob) {
                float bq0 = s_c3[ob*16 + qr];
                float bq8 = s_c3[ob*16 + qr + 8];
                float acc[2][2][4];
                #pragma unroll
                for (int pb = 0; pb < 2; ++pb)
                    #pragma unroll
                    for (int h = 0; h < 2; ++h) {
                        acc[pb][h][0] = bq0; acc[pb][h][1] = bq0;
                        acc[pb][h][2] = bq8; acc[pb][h][3] = bq8;
                    }
                #pragma unroll
                for (int kt = 0; kt < 4; ++kt) {
                    u32 a[4];
                    ldm4(a[0], a[1], a[2], a[3], w3base + ob*(16*RSTRIDE*2) + kt*32);
                    mma16816(acc[0][0], a, y2b[0][kt][0][0], y2b[0][kt][0][1]);
                    mma16816(acc[0][1], a, y2b[0][kt][1][0], y2b[0][kt][1][1]);
                    mma16816(acc[1][0], a, y2b[1][kt][0][0], y2b[1][kt][0][1]);
                    mma16816(acc[1][1], a, y2b[1][kt][1][0], y2b[1][kt][1][1]);
                }
                const int c0i = ob*16 + qr;
                #pragma unroll
                for (int pb = 0; pb < 2; ++pb)
                    #pragma unroll
                    for (int h = 0; h < 2; ++h) {
                        const int pcol = pb*16 + h*8 + qc;
                        float2 o;
                        o.x = fmaxf(acc[pb][h][0], 0.f) * vv[pb][h].x;
                        o.y = fmaxf(acc[pb][h][1], 0.f) * vv[pb][h].y;
                        *reinterpret_cast<float2*>(outb + (size_t)c0i*NPOS + pcol) = o;
                        o.x = fmaxf(acc[pb][h][2], 0.f) * vv[pb][h].x;
                        o.y = fmaxf(acc[pb][h][3], 0.f) * vv[pb][h].y;
                        *reinterpret_cast<float2*>(outb + (size_t)(c0i+8)*NPOS + pcol) = o;
                    }
            }
        }
    }
}

extern "C" void kernel_launch(void* const* d_in, const int* in_sizes, int n_in,
                              void* d_out, int out_size)
{
    (void)in_sizes; (void)n_in; (void)out_size;
    cudaFuncSetAttribute(pn_mma_kernel,
                         cudaFuncAttributeMaxDynamicSharedMemorySize, SMEM_TOTAL);
    pn_mma_kernel<<<NBLOCKS, THREADS, SMEM_TOTAL>>>(
        (const float*)d_in[0],  (const float*)d_in[1],
        (const float*)d_in[2],  (const float*)d_in[3],  (const float*)d_in[4],
        (const float*)d_in[5],  (const float*)d_in[6],  (const float*)d_in[7],
        (const float*)d_in[8],  (const float*)d_in[9],  (const float*)d_in[10],
        (const float*)d_in[11], (const float*)d_in[12], (const float*)d_in[13],
        (const float*)d_in[14], (const float*)d_in[15], (const float*)d_in[16],
        (const float*)d_in[17], (const float*)d_in[18], (const float*)d_in[19],
        (float*)d_out);
}

// round 9
// speedup vs baseline: 1.8969x; 1.8969x over previous
#include <cuda_runtime.h>
#include <cuda_fp16.h>
#include <cstdint>

typedef uint32_t u32;

#define NPOS    (4096*128)
#define TILE    256
#define NTILES  (NPOS/TILE)    // 2048
#define THREADS 256
#define NBLOCKS 296

#define RSTRIDE 72             // halves per row (144 B, ldmatrix conflict-free)

// ---- dynamic SMEM layout (bytes) ----
#define SM_W1F  0              // 64 x float4                  (1024)
#define SM_C2   1024           // 64 f                         (256)
#define SM_C3   1280           // 128 f                        (512)
#define SM_VAL  1792           // 2 x 256 f (double-buffered)  (2048)
#define SM_Y1   3840           // 2 x 256 x 72 halves          (73728)
#define SM_W2   77568          // 64  x 72 halves              (9216)
#define SM_W3   86784          // 128 x 72 halves              (18432)
#define SMEM_TOTAL 105216
#define Y1_BUF  36864

static __device__ __forceinline__ u32 sptr(const void* p) {
    u32 a;
    asm("{ .reg .u64 t; cvta.to.shared.u64 t, %1; cvt.u32.u64 %0, t; }" : "=r"(a) : "l"(p));
    return a;
}
static __device__ __forceinline__ void ldm4(u32& r0, u32& r1, u32& r2, u32& r3, u32 addr) {
    asm volatile("ldmatrix.sync.aligned.m8n8.x4.shared.b16 {%0,%1,%2,%3}, [%4];"
                 : "=r"(r0), "=r"(r1), "=r"(r2), "=r"(r3) : "r"(addr));
}
static __device__ __forceinline__ void mma16816(float c[4], const u32 a[4], u32 b0, u32 b1) {
    asm volatile("mma.sync.aligned.m16n8k16.row.col.f32.f16.f16.f32 "
                 "{%0,%1,%2,%3}, {%4,%5,%6,%7}, {%8,%9}, {%0,%1,%2,%3};"
                 : "+f"(c[0]), "+f"(c[1]), "+f"(c[2]), "+f"(c[3])
                 : "r"(a[0]), "r"(a[1]), "r"(a[2]), "r"(a[3]), "r"(b0), "r"(b1));
}
static __device__ __forceinline__ u32 pack2(float a, float b) {
    __half2 h = __floats2half2_rn(a, b);
    return *reinterpret_cast<u32*>(&h);
}

extern "C" __global__ void __launch_bounds__(THREADS, 2)
pn_mma_kernel(const float* __restrict__ pc,  const float* __restrict__ valid,
              const float* __restrict__ W1,  const float* __restrict__ b1,
              const float* __restrict__ g1,  const float* __restrict__ be1,
              const float* __restrict__ m1,  const float* __restrict__ v1,
              const float* __restrict__ W2,  const float* __restrict__ b2,
              const float* __restrict__ g2,  const float* __restrict__ be2,
              const float* __restrict__ m2,  const float* __restrict__ v2,
              const float* __restrict__ W3,  const float* __restrict__ b3,
              const float* __restrict__ g3,  const float* __restrict__ be3,
              const float* __restrict__ m3,  const float* __restrict__ v3,
              float* __restrict__ out)
{
    extern __shared__ char smem[];
    const u32 sb = sptr(smem);
    const int t    = threadIdx.x;
    const int lane = t & 31;
    const int w    = t >> 5;

    float*  s_w1f = reinterpret_cast<float*>(smem + SM_W1F);
    float*  s_c2  = reinterpret_cast<float*>(smem + SM_C2);
    float*  s_c3  = reinterpret_cast<float*>(smem + SM_C3);
    float*  s_val = reinterpret_cast<float*>(smem + SM_VAL);
    __half* s_w2  = reinterpret_cast<__half*>(smem + SM_W2);
    __half* s_w3  = reinterpret_cast<__half*>(smem + SM_W3);

    // ---- one-time prep: fold BN, convert weights to fp16 ----
    if (t < 64) {
        float inv1 = g1[t] * rsqrtf(v1[t] + 1e-5f);
        s_w1f[4*t+0] = W1[3*t+0]*inv1;
        s_w1f[4*t+1] = W1[3*t+1]*inv1;
        s_w1f[4*t+2] = W1[3*t+2]*inv1;
        s_w1f[4*t+3] = be1[t] + (b1[t] - m1[t]) * inv1;
        float inv2 = g2[t] * rsqrtf(v2[t] + 1e-5f);
        s_c2[t] = be2[t] + (b2[t] - m2[t]) * inv2;
    }
    if (t < 128) {
        float inv3 = g3[t] * rsqrtf(v3[t] + 1e-5f);
        s_c3[t] = be3[t] + (b3[t] - m3[t]) * inv3;
    }
    for (int i = t; i < 64*64; i += THREADS) {
        int n = i >> 6, k = i & 63;
        float inv2 = g2[n] * rsqrtf(v2[n] + 1e-5f);
        s_w2[n*RSTRIDE + k] = __float2half_rn(W2[i] * inv2);
    }
    for (int i = t; i < 128*64; i += THREADS) {
        int n = i >> 6, k = i & 63;
        float inv3 = g3[n] * rsqrtf(v3[n] + 1e-5f);
        s_w3[n*RSTRIDE + k] = __float2half_rn(W3[i] * inv3);
    }
    __syncthreads();

    // ---- per-thread fragment geometry ----
    const int qr  = lane >> 2;                            // accum row in 8
    const int qc  = (lane & 3) * 2;                       // accum col pair
    const int lr8 = (lane & 7) + ((lane >> 3) & 1) * 8;   // ldm4 row-in-16
    const int lc8 = (lane >> 4) * 8;                      // ldm4 k offset

    const u32 w2base = sb + SM_W2 + (u32)(((lane & 15)*RSTRIDE + lc8)*2);
    const u32 w3base = sb + SM_W3 + (u32)((lr8*RSTRIDE + lc8)*2);
    const u32 a2off0 = (u32)(((w*32 +      lr8)*RSTRIDE + lc8)*2);
    const u32 a2off1 = (u32)(((w*32 + 16 + lr8)*RSTRIDE + lc8)*2);
    const u32 y1off  = (u32)(t * RSTRIDE * 2);            // layer1: one pos per thread

    const int oddq  = lane & 1;                           // epilogue pairing parity
    const int colq  = (oddq << 3) + (((lane >> 1) & 1) << 2); // 0/4/8/12 within 16

    // ---- prefetch first tile ----
    int tile = blockIdx.x;
    float x0 = 0.f, x1 = 0.f, x2 = 0.f, vld = 0.f;
    if (tile < NTILES) {
        int px = tile*TILE + t;
        x0 = pc[px]; x1 = pc[NPOS + px]; x2 = pc[2*NPOS + px];
        vld = valid[px];
    }

    int it = 0;
    for (; tile < NTILES; tile += gridDim.x, ++it) {
        const int p0  = tile * TILE;
        const int buf = it & 1;
        const u32 y1b = sb + SM_Y1 + (u32)buf * Y1_BUF;

        // ---- layer 1: fp32 -> relu -> fp16 Y1[pos][k] (one pos / thread) ----
        {
            s_val[buf*TILE + t] = vld;
            const u32 dst = y1b + y1off;
            #pragma unroll
            for (int cb = 0; cb < 64; cb += 8) {
                u32 pk[4];
                #pragma unroll
                for (int q = 0; q < 4; ++q) {
                    int c0i = cb + 2*q;
                    float ya = fmaf(s_w1f[4*c0i+0], x0, fmaf(s_w1f[4*c0i+1], x1,
                               fmaf(s_w1f[4*c0i+2], x2, s_w1f[4*c0i+3])));
                    float yb = fmaf(s_w1f[4*c0i+4], x0, fmaf(s_w1f[4*c0i+5], x1,
                               fmaf(s_w1f[4*c0i+6], x2, s_w1f[4*c0i+7])));
                    pk[q] = pack2(fmaxf(ya, 0.f), fmaxf(yb, 0.f));
                }
                asm volatile("st.shared.v4.b32 [%0], {%1,%2,%3,%4};"
                             :: "r"(dst + cb*2), "r"(pk[0]), "r"(pk[1]), "r"(pk[2]), "r"(pk[3])
                             : "memory");
            }
        }
        __syncthreads();

        // ---- prefetch next tile (overlaps MMAs) ----
        {
            int ntile = tile + gridDim.x;
            x0 = x1 = x2 = vld = 0.f;
            if (ntile < NTILES) {
                int px = ntile*TILE + t;
                x0 = pc[px]; x1 = pc[NPOS + px]; x2 = pc[2*NPOS + px];
                vld = valid[px];
            }
        }

        // ---- layer 2: acc2[pb 2][nt 8][4], two pos blocks share each W2 frag ----
        float acc2[2][8][4];
        #pragma unroll
        for (int nt = 0; nt < 8; ++nt) {
            float2 bb = *reinterpret_cast<const float2*>(&s_c2[nt*8 + qc]);
            #pragma unroll
            for (int pb = 0; pb < 2; ++pb) {
                acc2[pb][nt][0] = bb.x; acc2[pb][nt][1] = bb.y;
                acc2[pb][nt][2] = bb.x; acc2[pb][nt][3] = bb.y;
            }
        }
        {
            const u32 a2b0 = y1b + a2off0;
            const u32 a2b1 = y1b + a2off1;
            #pragma unroll
            for (int kt = 0; kt < 4; ++kt) {
                u32 aA[4], aB[4];
                ldm4(aA[0], aA[1], aA[2], aA[3], a2b0 + kt*32);
                ldm4(aB[0], aB[1], aB[2], aB[3], a2b1 + kt*32);
                #pragma unroll
                for (int np = 0; np < 4; ++np) {
                    u32 b[4];
                    ldm4(b[0], b[1], b[2], b[3], w2base + np*(16*RSTRIDE*2) + kt*32);
                    // x4 fill: b0=(n0-7,klo) b1=(n8-15,klo) b2=(n0-7,khi) b3=(n8-15,khi)
                    mma16816(acc2[0][2*np],   aA, b[0], b[2]);
                    mma16816(acc2[0][2*np+1], aA, b[1], b[3]);
                    mma16816(acc2[1][2*np],   aB, b[0], b[2]);
                    mma16816(acc2[1][2*np+1], aB, b[1], b[3]);
                }
            }
        }

        // ---- relu+pack acc2 -> layer3 B fragments (registers) ----
        u32 y2b[2][4][2][2];
        #pragma unroll
        for (int pb = 0; pb < 2; ++pb)
            #pragma unroll
            for (int kt = 0; kt < 4; ++kt) {
                y2b[pb][kt][0][0] = pack2(fmaxf(acc2[pb][2*kt][0],   0.f), fmaxf(acc2[pb][2*kt][1],   0.f));
                y2b[pb][kt][0][1] = pack2(fmaxf(acc2[pb][2*kt+1][0], 0.f), fmaxf(acc2[pb][2*kt+1][1], 0.f));
                y2b[pb][kt][1][0] = pack2(fmaxf(acc2[pb][2*kt][2],   0.f), fmaxf(acc2[pb][2*kt][3],   0.f));
                y2b[pb][kt][1][1] = pack2(fmaxf(acc2[pb][2*kt+1][2], 0.f), fmaxf(acc2[pb][2*kt+1][3], 0.f));
            }

        // ---- layer 3: [out3 128][pos 32] per warp, coalesced STG.128 epilogue ----
        {
            float2 vv[2][2];
            #pragma unroll
            for (int pb = 0; pb < 2; ++pb) {
                vv[pb][0] = *reinterpret_cast<const float2*>(&s_val[buf*TILE + w*32 + pb*16 + qc]);
                vv[pb][1] = *reinterpret_cast<const float2*>(&s_val[buf*TILE + w*32 + pb*16 + 8 + qc]);
            }
            float* outb = out + (size_t)p0 + w*32;

            #pragma unroll
            for (int ob = 0; ob < 8; ++ob) {
                float bq0 = s_c3[ob*16 + qr];
                float bq8 = s_c3[ob*16 + qr + 8];
                float acc[2][2][4];
                #pragma unroll
                for (int pb = 0; pb < 2; ++pb)
                    #pragma unroll
                    for (int h = 0; h < 2; ++h) {
                        acc[pb][h][0] = bq0; acc[pb][h][1] = bq0;
                        acc[pb][h][2] = bq8; acc[pb][h][3] = bq8;
                    }
                #pragma unroll
                for (int kt = 0; kt < 4; ++kt) {
                    u32 a[4];
                    ldm4(a[0], a[1], a[2], a[3], w3base + ob*(16*RSTRIDE*2) + kt*32);
                    mma16816(acc[0][0], a, y2b[0][kt][0][0], y2b[0][kt][0][1]);
                    mma16816(acc[0][1], a, y2b[0][kt][1][0], y2b[0][kt][1][1]);
                    mma16816(acc[1][0], a, y2b[1][kt][0][0], y2b[1][kt][0][1]);
                    mma16816(acc[1][1], a, y2b[1][kt][1][0], y2b[1][kt][1][1]);
                }
                const int c0i = ob*16 + qr;
                #pragma unroll
                for (int pb = 0; pb < 2; ++pb) {
                    // relu * valid first (own columns), then lane-pair to 16B chunks
                    float r0 = fmaxf(acc[pb][0][0], 0.f) * vv[pb][0].x;  // row qr,   col qc   (h0)
                    float r1 = fmaxf(acc[pb][0][1], 0.f) * vv[pb][0].y;  // row qr,   col qc+1
                    float r2 = fmaxf(acc[pb][0][2], 0.f) * vv[pb][0].x;  // row qr+8, col qc
                    float r3 = fmaxf(acc[pb][0][3], 0.f) * vv[pb][0].y;
                    float s0 = fmaxf(acc[pb][1][0], 0.f) * vv[pb][1].x;  // row qr,   col 8+qc (h1)
                    float s1 = fmaxf(acc[pb][1][1], 0.f) * vv[pb][1].y;
                    float s2 = fmaxf(acc[pb][1][2], 0.f) * vv[pb][1].x;  // row qr+8
                    float s3 = fmaxf(acc[pb][1][3], 0.f) * vv[pb][1].y;
                    // even lane keeps h0 (sends its h1), odd lane keeps h1 (sends its h0)
                    float m0 = oddq ? r0 : s0;
                    float m1 = oddq ? r1 : s1;
                    float m2 = oddq ? r2 : s2;
                    float m3 = oddq ? r3 : s3;
                    float g0 = __shfl_xor_sync(0xffffffffu, m0, 1);
                    float g1 = __shfl_xor_sync(0xffffffffu, m1, 1);
                    float g2 = __shfl_xor_sync(0xffffffffu, m2, 1);
                    float g3 = __shfl_xor_sync(0xffffffffu, m3, 1);
                    float4 t0, t1;
                    t0.x = oddq ? g0 : r0;  t0.y = oddq ? g1 : r1;
                    t0.z = oddq ? s0 : g0;  t0.w = oddq ? s1 : g1;
                    t1.x = oddq ? g2 : r2;  t1.y = oddq ? g3 : r3;
                    t1.z = oddq ? s2 : g2;  t1.w = oddq ? s3 : g3;
                    const int colb = pb*16 + colq;
                    *reinterpret_cast<float4*>(outb + (size_t)c0i*NPOS + colb)     = t0;
                    *reinterpret_cast<float4*>(outb + (size_t)(c0i+8)*NPOS + colb) = t1;
                }
            }
        }
        // no trailing barrier: Y1/val double-buffered
    }
}

extern "C" void kernel_launch(void* const* d_in, const int* in_sizes, int n_in,
                              void* d_out, int out_size)
{
    (void)in_sizes; (void)n_in; (void)out_size;
    cudaFuncSetAttribute(pn_mma_kernel,
                         cudaFuncAttributeMaxDynamicSharedMemorySize, SMEM_TOTAL);
    pn_mma_kernel<<<NBLOCKS, THREADS, SMEM_TOTAL>>>(
        (const float*)d_in[0],  (const float*)d_in[1],
        (const float*)d_in[2],  (const float*)d_in[3],  (const float*)d_in[4],
        (const float*)d_in[5],  (const float*)d_in[6],  (const float*)d_in[7],
        (const float*)d_in[8],  (const float*)d_in[9],  (const float*)d_in[10],
        (const float*)d_in[11], (const float*)d_in[12], (const float*)d_in[13],
        (const float*)d_in[14], (const float*)d_in[15], (const float*)d_in[16],
        (const float*)d_in[17], (const float*)d_in[18], (const float*)d_in[19],
        (float*)d_out);
}